// round 4
// baseline (speedup 1.0000x reference)
#include <cuda_runtime.h>
#include <cuda_bf16.h>
#include <cstdint>

// input_spikes: [B=32, C=3, H=128, W=128, T=50] f32; weight/gain/bias: [C,H,W]
// Output = spikes [B,C,H,W,T] ++ final_v [B,C,H,W] ++ final_reset [B,C,H,W]

#define T_STEPS       50
#define PIX_PER_BLK   128
#define REGION_FLOATS (PIX_PER_BLK * T_STEPS)    // 6400
#define REGION_BYTES  (REGION_FLOATS * 4)        // 25600
#define NBUF          4
#define NUM_REGIONS   12288                      // TOTAL_PIX / PIX_PER_BLK
#define CHW           49152                      // 3*128*128
#define TOTAL_PIX     1572864                    // 32*49152
#define SPIKES_ELEMS  78643200LL
#define GRID_CTAS     304                        // ~2 per SM, grid-stride over regions
#define SMEM_DYN_BYTES (NBUF * REGION_BYTES + 64)

__device__ __forceinline__ float lif_decay() { return 0.77880078307140486825f; }

__device__ __forceinline__ void mbar_wait(uint32_t mbar, uint32_t parity) {
    uint32_t done;
    asm volatile(
        "{\n\t.reg .pred p;\n\t"
        "mbarrier.try_wait.parity.acquire.cta.shared::cta.b64 p, [%1], %2;\n\t"
        "selp.b32 %0, 1, 0, p;\n\t}"
        : "=r"(done) : "r"(mbar), "r"(parity) : "memory");
    if (!done) {
        asm volatile(
            "{\n\t.reg .pred P1;\n\t"
            "WAIT_LOOP_%=:\n\t"
            "mbarrier.try_wait.parity.acquire.cta.shared::cta.b64 P1, [%0], %1, 0x989680;\n\t"
            "@P1 bra.uni WAIT_DONE_%=;\n\t"
            "bra.uni WAIT_LOOP_%=;\n\t"
            "WAIT_DONE_%=:\n\t}"
            :: "r"(mbar), "r"(parity) : "memory");
    }
}

__device__ __forceinline__ void issue_load(uint32_t mbar, uint32_t smem_dst,
                                           const float* src) {
    asm volatile("mbarrier.arrive.expect_tx.shared.b64 _, [%0], %1;"
                 :: "r"(mbar), "r"(REGION_BYTES) : "memory");
    asm volatile(
        "cp.async.bulk.shared::cta.global.mbarrier::complete_tx::bytes "
        "[%0], [%1], %2, [%3];"
        :: "r"(smem_dst), "l"(src), "r"(REGION_BYTES), "r"(mbar) : "memory");
}

__global__ void __launch_bounds__(PIX_PER_BLK)
lif_persistent(const float* __restrict__ x,
               const float* __restrict__ w,
               const float* __restrict__ g,
               float* __restrict__ out_spikes,
               float* __restrict__ out_final_v,
               float* __restrict__ out_final_r)
{
    extern __shared__ __align__(128) float smem[];
    uint64_t* mbars = reinterpret_cast<uint64_t*>(smem + NBUF * REGION_FLOATS);

    const int tid = threadIdx.x;
    const int bid = blockIdx.x;
    const int G   = gridDim.x;

    // number of regions this CTA handles (regions: bid, bid+G, bid+2G, ...)
    const int n = (NUM_REGIONS - bid + G - 1) / G;

    const uint32_t smem_base = (uint32_t)__cvta_generic_to_shared(smem);
    const uint32_t mbar_base = (uint32_t)__cvta_generic_to_shared(mbars);

    if (tid == 0) {
        #pragma unroll
        for (int b = 0; b < NBUF; ++b)
            asm volatile("mbarrier.init.shared.b64 [%0], %1;"
                         :: "r"(mbar_base + 8u * b), "r"(1) : "memory");
        asm volatile("fence.proxy.async.shared::cta;" ::: "memory");
    }
    __syncthreads();

    // ---- prologue: fill pipeline with up to 2 loads ----
    if (tid == 0) {
        const int pre = (n < 2) ? n : 2;
        for (int j = 0; j < pre; ++j) {
            long long region = bid + (long long)j * G;
            issue_load(mbar_base + 8u * j,
                       smem_base + (uint32_t)(j * REGION_BYTES),
                       x + region * T_STEPS * PIX_PER_BLK);
        }
    }

    const float decay = lif_decay();
    const float omd   = 1.0f - decay;

    for (int i = 0; i < n; ++i) {
        const int b      = i & (NBUF - 1);
        const int parity = (i >> 2) & 1;
        mbar_wait(mbar_base + 8u * b, parity);

        const long long region   = bid + (long long)i * G;
        const long long base_pix = region * PIX_PER_BLK;
        const long long gp       = base_pix + tid;
        const int       chw      = (int)(gp % CHW);

        const float wv = w[chw];
        const float gv = g[chw];

        float* sb = smem + b * REGION_FLOATS;
        float2* srow = reinterpret_cast<float2*>(sb + tid * T_STEPS); // 8B aligned

        float v = 0.0f, r = 0.0f;
        #pragma unroll
        for (int t2 = 0; t2 < T_STEPS / 2; ++t2) {
            float2 xx = srow[t2];

            float wp0 = wv * xx.x;
            v = v * decay + gv * wp0 * omd;        // reference op order
            float sp0 = (v > 1.0f) ? 1.0f : 0.0f;
            r = r * decay + sp0;

            float wp1 = wv * xx.y;
            v = v * decay + gv * wp1 * omd;
            float sp1 = (v > 1.0f) ? 1.0f : 0.0f;
            r = r * decay + sp1;

            srow[t2] = make_float2(sp0, sp1);
        }
        out_final_v[gp] = v;
        out_final_r[gp] = r;

        __syncthreads();   // all spikes in smem before async-proxy store reads

        if (tid == 0) {
            asm volatile("fence.proxy.async.shared::cta;" ::: "memory");
            float* dst = out_spikes + base_pix * T_STEPS;
            asm volatile(
                "cp.async.bulk.global.shared::cta.bulk_group [%0], [%1], %2;"
                :: "l"(dst),
                   "r"(smem_base + (uint32_t)(b * REGION_BYTES)),
                   "r"(REGION_BYTES) : "memory");
            asm volatile("cp.async.bulk.commit_group;" ::: "memory");

            const int inext = i + 2;
            if (inext < n) {
                // buffer (inext&3) was stored at iter i-2; allow the 2 newest
                // store groups (i, i-1) outstanding, wait for i-2 and older.
                asm volatile("cp.async.bulk.wait_group 2;" ::: "memory");
                long long nreg = bid + (long long)inext * G;
                issue_load(mbar_base + 8u * (inext & (NBUF - 1)),
                           smem_base + (uint32_t)((inext & (NBUF - 1)) * REGION_BYTES),
                           x + nreg * T_STEPS * PIX_PER_BLK);
            }
        }
    }

    // drain outstanding stores before smem is released
    if (tid == 0)
        asm volatile("cp.async.bulk.wait_group 0;" ::: "memory");
}

extern "C" void kernel_launch(void* const* d_in, const int* in_sizes, int n_in,
                              void* d_out, int out_size)
{
    const float* x = (const float*)d_in[0];   // input_spikes
    const float* w = (const float*)d_in[1];   // weight
    const float* g = (const float*)d_in[2];   // gain
    // d_in[3] = bias: unused by the reference computation

    float* out        = (float*)d_out;
    float* out_spikes = out;
    float* out_vf     = out + SPIKES_ELEMS;
    float* out_rf     = out + SPIKES_ELEMS + TOTAL_PIX;

    cudaFuncSetAttribute(lif_persistent,
                         cudaFuncAttributeMaxDynamicSharedMemorySize,
                         SMEM_DYN_BYTES);

    lif_persistent<<<GRID_CTAS, PIX_PER_BLK, SMEM_DYN_BYTES>>>(
        x, w, g, out_spikes, out_vf, out_rf);
}

// round 5
// speedup vs baseline: 1.0135x; 1.0135x over previous
#include <cuda_runtime.h>
#include <cuda_bf16.h>
#include <cstdint>

// input_spikes: [B=32, C=3, H=128, W=128, T=50] f32; weight/gain/bias: [C,H,W]
// Output = spikes [B,C,H,W,T] ++ final_v [B,C,H,W] ++ final_reset [B,C,H,W]

#define T_STEPS       50
#define PIX_PER_BLK   128
#define REGION_FLOATS (PIX_PER_BLK * T_STEPS)    // 6400
#define REGION_BYTES  (REGION_FLOATS * 4)        // 25600
#define REGIONS_PER_CTA 2
#define CHW           49152                      // 3*128*128
#define TOTAL_PIX     1572864                    // 32*49152
#define SPIKES_ELEMS  78643200LL
#define NUM_CTAS      6144                       // TOTAL_PIX / (128*2)

__device__ __forceinline__ float lif_decay() { return 0.77880078307140486825f; }

__device__ __forceinline__ void mbar_wait0(uint32_t mbar) {
    uint32_t done;
    asm volatile(
        "{\n\t.reg .pred p;\n\t"
        "mbarrier.try_wait.parity.acquire.cta.shared::cta.b64 p, [%1], 0;\n\t"
        "selp.b32 %0, 1, 0, p;\n\t}"
        : "=r"(done) : "r"(mbar) : "memory");
    if (!done) {
        asm volatile(
            "{\n\t.reg .pred P1;\n\t"
            "WAIT_LOOP_%=:\n\t"
            "mbarrier.try_wait.parity.acquire.cta.shared::cta.b64 P1, [%0], 0, 0x989680;\n\t"
            "@P1 bra.uni WAIT_DONE_%=;\n\t"
            "bra.uni WAIT_LOOP_%=;\n\t"
            "WAIT_DONE_%=:\n\t}"
            :: "r"(mbar) : "memory");
    }
}

__global__ void __launch_bounds__(PIX_PER_BLK)
lif_kernel(const float* __restrict__ x,
           const float* __restrict__ w,
           const float* __restrict__ g,
           float* __restrict__ out_spikes,
           float* __restrict__ out_final_v,
           float* __restrict__ out_final_r)
{
    __shared__ __align__(128) float s[REGIONS_PER_CTA * REGION_FLOATS]; // 51,200 B
    __shared__ __align__(8)   uint64_t mbar[REGIONS_PER_CTA];

    const int tid = threadIdx.x;
    const long long region0 = (long long)blockIdx.x * REGIONS_PER_CTA;

    const uint32_t smem_s    = (uint32_t)__cvta_generic_to_shared(s);
    const uint32_t smem_mbar = (uint32_t)__cvta_generic_to_shared(mbar);

    // ---- init barriers, then issue BOTH region loads immediately ----
    if (tid == 0) {
        #pragma unroll
        for (int j = 0; j < REGIONS_PER_CTA; ++j)
            asm volatile("mbarrier.init.shared.b64 [%0], %1;"
                         :: "r"(smem_mbar + 8u * j), "r"(1) : "memory");
        asm volatile("fence.proxy.async.shared::cta;" ::: "memory");
        #pragma unroll
        for (int j = 0; j < REGIONS_PER_CTA; ++j) {
            asm volatile("mbarrier.arrive.expect_tx.shared.b64 _, [%0], %1;"
                         :: "r"(smem_mbar + 8u * j), "r"(REGION_BYTES) : "memory");
            const float* src = x + (region0 + j) * (long long)REGION_FLOATS;
            asm volatile(
                "cp.async.bulk.shared::cta.global.mbarrier::complete_tx::bytes "
                "[%0], [%1], %2, [%3];"
                :: "r"(smem_s + (uint32_t)(j * REGION_BYTES)),
                   "l"(src), "r"(REGION_BYTES),
                   "r"(smem_mbar + 8u * j)
                : "memory");
        }
    }
    __syncthreads();

    const float decay = lif_decay();
    const float omd   = 1.0f - decay;

    #pragma unroll
    for (int j = 0; j < REGIONS_PER_CTA; ++j) {
        mbar_wait0(smem_mbar + 8u * j);

        const long long base_pix = (region0 + j) * PIX_PER_BLK;
        const long long gp       = base_pix + tid;
        const int       chw      = (int)(gp % CHW);

        const float wv = w[chw];
        const float gv = g[chw];

        // thread's row: byte offset j*25600 + tid*200 -> 8B aligned
        float2* srow = reinterpret_cast<float2*>(s + j * REGION_FLOATS + tid * T_STEPS);

        float v = 0.0f, r = 0.0f;
        #pragma unroll
        for (int t2 = 0; t2 < T_STEPS / 2; ++t2) {
            float2 xx = srow[t2];

            float wp0 = wv * xx.x;
            v = v * decay + gv * wp0 * omd;        // reference op order
            float sp0 = (v > 1.0f) ? 1.0f : 0.0f;
            r = r * decay + sp0;

            float wp1 = wv * xx.y;
            v = v * decay + gv * wp1 * omd;
            float sp1 = (v > 1.0f) ? 1.0f : 0.0f;
            r = r * decay + sp1;

            srow[t2] = make_float2(sp0, sp1);
        }
        out_final_v[gp] = v;
        out_final_r[gp] = r;

        __syncthreads();   // all spikes of this region in smem before async store

        if (tid == 0) {
            asm volatile("fence.proxy.async.shared::cta;" ::: "memory");
            float* dst = out_spikes + base_pix * (long long)T_STEPS;
            asm volatile(
                "cp.async.bulk.global.shared::cta.bulk_group [%0], [%1], %2;"
                :: "l"(dst),
                   "r"(smem_s + (uint32_t)(j * REGION_BYTES)),
                   "r"(REGION_BYTES) : "memory");
            asm volatile("cp.async.bulk.commit_group;" ::: "memory");
        }
    }

    // drain both outstanding stores before smem is released
    if (tid == 0)
        asm volatile("cp.async.bulk.wait_group 0;" ::: "memory");
}

extern "C" void kernel_launch(void* const* d_in, const int* in_sizes, int n_in,
                              void* d_out, int out_size)
{
    const float* x = (const float*)d_in[0];   // input_spikes
    const float* w = (const float*)d_in[1];   // weight
    const float* g = (const float*)d_in[2];   // gain
    // d_in[3] = bias: unused by the reference computation

    float* out        = (float*)d_out;
    float* out_spikes = out;
    float* out_vf     = out + SPIKES_ELEMS;
    float* out_rf     = out + SPIKES_ELEMS + TOTAL_PIX;

    lif_kernel<<<NUM_CTAS, PIX_PER_BLK>>>(x, w, g, out_spikes, out_vf, out_rf);
}